// round 4
// baseline (speedup 1.0000x reference)
#include <cuda_runtime.h>
#include <cuda_bf16.h>
#include <cstdint>

// Problem constants
#define Bn   16
#define Nn   4096
#define Mn   1024
#define C1n  128
#define C2n  256
#define CINn 384
#define H1n  256
#define H2n  128

#define PITCH 144   // bytes per smem row (72 bf16): conflict-free ldmatrix

// ---------------- helpers ----------------
__device__ __forceinline__ uint32_t smem_u32(const void* p) {
    uint32_t a;
    asm("{ .reg .u64 t; cvta.to.shared.u64 t, %1; cvt.u32.u64 %0, t; }" : "=r"(a) : "l"(p));
    return a;
}
__device__ __forceinline__ void ldsm4(uint32_t* r, uint32_t addr) {
    asm volatile("ldmatrix.sync.aligned.m8n8.x4.shared.b16 {%0,%1,%2,%3}, [%4];"
        : "=r"(r[0]), "=r"(r[1]), "=r"(r[2]), "=r"(r[3]) : "r"(addr));
}
__device__ __forceinline__ void ldsm4t(uint32_t* r, uint32_t addr) {
    asm volatile("ldmatrix.sync.aligned.m8n8.x4.trans.shared.b16 {%0,%1,%2,%3}, [%4];"
        : "=r"(r[0]), "=r"(r[1]), "=r"(r[2]), "=r"(r[3]) : "r"(addr));
}
__device__ __forceinline__ void mma_bf16(float* d, const uint32_t* a, const uint32_t* b) {
    asm volatile("mma.sync.aligned.m16n8k16.row.col.f32.bf16.bf16.f32 "
        "{%0,%1,%2,%3}, {%4,%5,%6,%7}, {%8,%9}, {%0,%1,%2,%3};"
        : "+f"(d[0]), "+f"(d[1]), "+f"(d[2]), "+f"(d[3])
        : "r"(a[0]), "r"(a[1]), "r"(a[2]), "r"(a[3]), "r"(b[0]), "r"(b[1]));
}
__device__ __forceinline__ uint32_t bfhi2(float a, float b) {
    return __byte_perm(__float_as_uint(a), __float_as_uint(b), 0x7632);
}
__device__ __forceinline__ uint32_t bflo2(float a, float b) {
    const float la = a - __uint_as_float(__float_as_uint(a) & 0xFFFF0000u);
    const float lb = b - __uint_as_float(__float_as_uint(b) & 0xFFFF0000u);
    __nv_bfloat162 p = __floats2bfloat162_rn(la, lb);
    return *(uint32_t*)&p;
}
__device__ __forceinline__ uint16_t bfhi1(float a) {
    return (uint16_t)(__float_as_uint(a) >> 16);
}
__device__ __forceinline__ uint16_t bflo1(float a) {
    const float l = a - __uint_as_float(__float_as_uint(a) & 0xFFFF0000u);
    __nv_bfloat16 h = __float2bfloat16(l);
    return *(uint16_t*)&h;
}
#define CP16(dst, src) asm volatile("cp.async.cg.shared.global [%0], [%1], 16;" :: "r"(dst), "l"(src))
#define CPCOMMIT()     asm volatile("cp.async.commit_group;" ::: "memory")
#define CPWAIT(n)      asm volatile("cp.async.wait_group %0;" :: "n"(n) : "memory")

// ---------------- device scratch (bf16 bit patterns as u16) ----------------
__device__ uint16_t g_p2h[(size_t)Bn * C2n * Mn];
__device__ uint16_t g_p2l[(size_t)Bn * C2n * Mn];
__device__ uint16_t g_p1h[(size_t)Bn * C1n * Nn];
__device__ uint16_t g_p1l[(size_t)Bn * C1n * Nn];
__device__ uint16_t g_w1h[H1n * CINn];
__device__ uint16_t g_w1l[H1n * CINn];
__device__ uint16_t g_w2h[H2n * H1n];
__device__ uint16_t g_w2l[H2n * H1n];
__device__ uint16_t g_xh[(size_t)Bn * C2n * Nn];   // interp output hi
__device__ uint16_t g_xl[(size_t)Bn * C2n * Nn];   // interp output lo

// ---------------- prep: generic fp32 -> bf16 hi/lo split ----------------
__global__ void split_kernel(const float* __restrict__ src,
                             uint16_t* __restrict__ dh,
                             uint16_t* __restrict__ dl)
{
    const size_t i = (size_t)blockIdx.x * 256 + threadIdx.x;   // float4 index
    const float4 v = ((const float4*)src)[i];
    uint2 h, l;
    h.x = bfhi2(v.x, v.y); h.y = bfhi2(v.z, v.w);
    l.x = bflo2(v.x, v.y); l.y = bflo2(v.z, v.w);
    ((uint2*)dh)[i] = h;
    ((uint2*)dl)[i] = l;
}

// ================= Kernel 1: interpolation via mma.sync =================
// CTA tile: 64 n x 256 c, K = M = 1024 in 64-chunks, cp.async double-buffered.
#define IA(buf, part)  ((buf) * 18432 + (part) * 9216)
#define IB(buf, part)  (36864 + (buf) * 73728 + (part) * 36864)
#define IOFF_X2  184320
#define IOFF_DS  196608
#define IOFF_DEN 197632
#define ISMB     197888

__global__ __launch_bounds__(256, 1)
void interp_tc(const float* __restrict__ xyz1,
               const float* __restrict__ xyz2)
{
    extern __shared__ char smc[];
    const uint32_t sb = smem_u32(smc);
    float* s_x2  = (float*)(smc + IOFF_X2);
    float* s_ds  = (float*)(smc + IOFF_DS);
    float* s_den = (float*)(smc + IOFF_DEN);

    const int tid = threadIdx.x, w = tid >> 5, lane = tid & 31;
    const int b = blockIdx.y, n0 = blockIdx.x * 64;

    for (int i = tid; i < Mn * 3; i += 256)
        s_x2[i] = xyz2[(size_t)b * Mn * 3 + i];
    __syncthreads();

    const int nf = tid & 63;
    const int g  = tid >> 6;
    const float px = xyz1[((size_t)b * Nn + n0 + nf) * 3 + 0];
    const float py = xyz1[((size_t)b * Nn + n0 + nf) * 3 + 1];
    const float pz = xyz1[((size_t)b * Nn + n0 + nf) * 3 + 2];
    float dsum = 0.f;

    const int mw = w & 1, cw = w >> 1;
    float acc[16][4];
    #pragma unroll
    for (int i = 0; i < 16; i++)
        #pragma unroll
        for (int j = 0; j < 4; j++) acc[i][j] = 0.f;

    const size_t p2base = (size_t)b * C2n * Mn;   // u16 elements

    // A fill: SIMT rsqrt weights, hi/lo
    #define FILLA(ch) do {                                                         \
        const int _buf = (ch) & 1, _m0 = (ch) * 64;                                \
        _Pragma("unroll")                                                          \
        for (int j = 0; j < 2; j++) {                                              \
            const int mb = g * 16 + j * 8;                                         \
            float iv[8];                                                           \
            _Pragma("unroll")                                                      \
            for (int t = 0; t < 8; t++) {                                          \
                const int m = _m0 + mb + t;                                        \
                const float dx = px - s_x2[m * 3 + 0];                             \
                const float dy = py - s_x2[m * 3 + 1];                             \
                const float dz = pz - s_x2[m * 3 + 2];                             \
                const float d2 = fmaf(dx, dx, fmaf(dy, dy, fmaf(dz, dz, 1e-16f))); \
                iv[t] = rsqrtf(d2);                                                \
                dsum += iv[t];                                                     \
            }                                                                      \
            uint4 hv, lv;                                                          \
            hv.x = bfhi2(iv[0], iv[1]); hv.y = bfhi2(iv[2], iv[3]);                \
            hv.z = bfhi2(iv[4], iv[5]); hv.w = bfhi2(iv[6], iv[7]);                \
            lv.x = bflo2(iv[0], iv[1]); lv.y = bflo2(iv[2], iv[3]);                \
            lv.z = bflo2(iv[4], iv[5]); lv.w = bflo2(iv[6], iv[7]);                \
            *(uint4*)(smc + IA(_buf, 0) + nf * PITCH + mb * 2) = hv;               \
            *(uint4*)(smc + IA(_buf, 1) + nf * PITCH + mb * 2) = lv;               \
        }                                                                          \
    } while (0)

    // B fill: cp.async of pre-split p2 chunk [256 c][64 m] hi/lo
    #define FILLB(ch) do {                                                         \
        const int _buf = (ch) & 1, _m0 = (ch) * 64;                                \
        _Pragma("unroll")                                                          \
        for (int it = 0; it < 16; it++) {                                          \
            const int u = tid + it * 256;                                          \
            const int part = u >> 11;                                              \
            const int v = u & 2047, c = v >> 3, s = v & 7;                         \
            const uint32_t dst = sb + IB(_buf, part) + c * PITCH + s * 16;         \
            const uint16_t* srcb = part ? g_p2l : g_p2h;                           \
            CP16(dst, srcb + p2base + (size_t)c * Mn + _m0 + s * 8);               \
        }                                                                          \
        CPCOMMIT();                                                                \
    } while (0)

    FILLA(0); FILLB(0);
    FILLA(1); FILLB(1);

    for (int ch = 0; ch < 16; ch++) {
        const int buf = ch & 1;
        if (ch < 15) { CPWAIT(1); } else { CPWAIT(0); }
        __syncthreads();
        // ---- MMA on buf ----
        #pragma unroll
        for (int kk = 0; kk < 4; kk++) {
            uint32_t ah[2][4], al[2][4];
            #pragma unroll
            for (int mt = 0; mt < 2; mt++) {
                const uint32_t row = mw * 32 + mt * 16 + (lane & 15);
                const uint32_t off = row * PITCH + kk * 32 + (lane >> 4) * 16;
                ldsm4(ah[mt], sb + IA(buf, 0) + off);
                ldsm4(al[mt], sb + IA(buf, 1) + off);
            }
            uint32_t bh[8][2], bl[8][2];
            #pragma unroll
            for (int cp = 0; cp < 4; cp++) {
                const uint32_t row = cw * 64 + cp * 16 + (lane >> 4) * 8 + (lane & 7);
                const uint32_t off = row * PITCH + kk * 32 + ((lane >> 3) & 1) * 16;
                uint32_t r[4];
                ldsm4(r, sb + IB(buf, 0) + off);
                bh[cp * 2][0] = r[0]; bh[cp * 2][1] = r[1];
                bh[cp * 2 + 1][0] = r[2]; bh[cp * 2 + 1][1] = r[3];
                ldsm4(r, sb + IB(buf, 1) + off);
                bl[cp * 2][0] = r[0]; bl[cp * 2][1] = r[1];
                bl[cp * 2 + 1][0] = r[2]; bl[cp * 2 + 1][1] = r[3];
            }
            #pragma unroll
            for (int mt = 0; mt < 2; mt++)
                #pragma unroll
                for (int ct = 0; ct < 8; ct++) {
                    mma_bf16(acc[mt * 8 + ct], ah[mt], bh[ct]);
                    mma_bf16(acc[mt * 8 + ct], ah[mt], bl[ct]);
                    mma_bf16(acc[mt * 8 + ct], al[mt], bh[ct]);
                }
        }
        if (ch < 14) {
            __syncthreads();
            FILLA(ch + 2);
            FILLB(ch + 2);
        }
    }
    #undef FILLA
    #undef FILLB

    // denominator
    __syncthreads();
    s_ds[tid] = dsum;
    __syncthreads();
    if (tid < 64)
        s_den[tid] = 1.0f / (s_ds[tid] + s_ds[tid + 64] + s_ds[tid + 128] + s_ds[tid + 192]);
    __syncthreads();

    // epilogue: scale, split to bf16 hi/lo, store
    #pragma unroll
    for (int mt = 0; mt < 2; mt++) {
        const int nl = mw * 32 + mt * 16 + (lane >> 2);
        const float i0 = s_den[nl], i1 = s_den[nl + 8];
        #pragma unroll
        for (int ct = 0; ct < 8; ct++) {
            const int c = cw * 64 + ct * 8 + (lane & 3) * 2;
            const size_t b0 = ((size_t)b * C2n + c) * Nn + n0;
            const size_t b1 = b0 + Nn;
            const float* a = acc[mt * 8 + ct];
            const float v00 = a[0] * i0, v01 = a[1] * i0;
            const float v10 = a[2] * i1, v11 = a[3] * i1;
            g_xh[b0 + nl]     = bfhi1(v00);  g_xl[b0 + nl]     = bflo1(v00);
            g_xh[b1 + nl]     = bfhi1(v01);  g_xl[b1 + nl]     = bflo1(v01);
            g_xh[b0 + nl + 8] = bfhi1(v10);  g_xl[b0 + nl + 8] = bflo1(v10);
            g_xh[b1 + nl + 8] = bfhi1(v11);  g_xl[b1 + nl + 8] = bflo1(v11);
        }
    }
}

// ================= Kernel 2: fused 2-layer MLP via mma.sync =================
#define MW(buf, part)   ((buf) * 73728 + (part) * 36864)         // W1 chunk [256][72]
#define MX(buf, part)   (147456 + (buf) * 18432 + (part) * 9216) // x chunk [64][72]
#define MH(part)        ((part) * 36864)                          // h [256][72] (overlays MW)
#define MW2(buf, part)  (147456 + (buf) * 36864 + (part) * 18432) // W2 chunk [128][72]
#define MOFF_B1  221184
#define MOFF_B2  222208
#define MSMB     222720

__global__ __launch_bounds__(256, 1)
void mlp_tc(const float* __restrict__ b1,
            const float* __restrict__ b2,
            float* __restrict__ out)
{
    extern __shared__ char smc[];
    const uint32_t sb = smem_u32(smc);
    float* s_b1 = (float*)(smc + MOFF_B1);
    float* s_b2 = (float*)(smc + MOFF_B2);

    const int tid = threadIdx.x, w = tid >> 5, lane = tid & 31;
    const int b = blockIdx.y, n0 = blockIdx.x * 64;

    s_b1[tid] = b1[tid];
    if (tid < H2n) s_b2[tid] = b2[tid];

    const int ow = w >> 1, nw = w & 1;

    // W1 chunk fill via cp.async: 2 parts x 256 rows x 8 segs
    #define FILLW1(kc) do {                                                         \
        const int _buf = (kc) & 1;                                                  \
        _Pragma("unroll")                                                           \
        for (int it = 0; it < 16; it++) {                                           \
            const int u = tid + it * 256;                                           \
            const int part = u >> 11;                                               \
            const int v = u & 2047, o = v >> 3, s = v & 7;                          \
            const uint32_t dst = sb + MW(_buf, part) + o * PITCH + s * 16;          \
            const uint16_t* srcb = part ? g_w1l : g_w1h;                            \
            CP16(dst, srcb + o * CINn + (kc) * 64 + s * 8);                         \
        }                                                                           \
    } while (0)

    // x chunk fill via cp.async: 2 parts x 64 rows x 8 segs (from p1 or interp)
    #define FILLX(kc) do {                                                          \
        const int _buf = (kc) & 1;                                                  \
        _Pragma("unroll")                                                           \
        for (int it = 0; it < 4; it++) {                                            \
            const int u = tid + it * 256;                                           \
            const int part = u >> 9;                                                \
            const int v = u & 511, k = v >> 3, s = v & 7;                           \
            const int c = (kc) * 64 + k;                                            \
            const uint32_t dst = sb + MX(_buf, part) + k * PITCH + s * 16;          \
            const uint16_t* srcb = (c < C1n)                                        \
                ? ((part ? g_p1l : g_p1h) + ((size_t)b * C1n + c) * Nn)             \
                : ((part ? g_xl : g_xh) + ((size_t)b * C2n + (c - C1n)) * Nn);      \
            CP16(dst, srcb + n0 + s * 8);                                           \
        }                                                                           \
        CPCOMMIT();                                                                 \
    } while (0)

    float acc1[16][4];
    #pragma unroll
    for (int i = 0; i < 16; i++)
        #pragma unroll
        for (int j = 0; j < 4; j++) acc1[i][j] = 0.f;

    FILLW1(0); FILLX(0);
    FILLW1(1); FILLX(1);

    for (int kc = 0; kc < 6; kc++) {
        const int buf = kc & 1;
        if (kc < 5) { CPWAIT(1); } else { CPWAIT(0); }
        __syncthreads();
        #pragma unroll
        for (int kk = 0; kk < 4; kk++) {
            uint32_t wh[4][4], wl[4][4];
            #pragma unroll
            for (int mi = 0; mi < 4; mi++) {
                const uint32_t row = ow * 64 + mi * 16 + (lane & 15);
                const uint32_t off = row * PITCH + kk * 32 + (lane >> 4) * 16;
                ldsm4(wh[mi], sb + MW(buf, 0) + off);
                ldsm4(wl[mi], sb + MW(buf, 1) + off);
            }
            uint32_t xh[4][2], xl[4][2];
            #pragma unroll
            for (int np = 0; np < 2; np++) {
                const uint32_t row  = kk * 16 + ((lane >> 3) & 1) * 8 + (lane & 7);
                const uint32_t colb = (nw * 32 + np * 16) * 2 + (lane >> 4) * 16;
                uint32_t r[4];
                ldsm4t(r, sb + MX(buf, 0) + row * PITCH + colb);
                xh[np * 2][0] = r[0]; xh[np * 2][1] = r[1];
                xh[np * 2 + 1][0] = r[2]; xh[np * 2 + 1][1] = r[3];
                ldsm4t(r, sb + MX(buf, 1) + row * PITCH + colb);
                xl[np * 2][0] = r[0]; xl[np * 2][1] = r[1];
                xl[np * 2 + 1][0] = r[2]; xl[np * 2 + 1][1] = r[3];
            }
            #pragma unroll
            for (int mi = 0; mi < 4; mi++)
                #pragma unroll
                for (int ni = 0; ni < 4; ni++) {
                    mma_bf16(acc1[mi * 4 + ni], wh[mi], xh[ni]);
                    mma_bf16(acc1[mi * 4 + ni], wh[mi], xl[ni]);
                    mma_bf16(acc1[mi * 4 + ni], wl[mi], xh[ni]);
                }
        }
        if (kc < 4) {
            __syncthreads();
            FILLW1(kc + 2);
            FILLX(kc + 2);
        }
    }
    #undef FILLW1
    #undef FILLX

    __syncthreads();   // GEMM1 reads done everywhere

    // W2 chunk fill via cp.async: 2 parts x 128 rows x 8 segs
    #define FILLW2(kc) do {                                                         \
        const int _buf = (kc) & 1;                                                  \
        _Pragma("unroll")                                                           \
        for (int it = 0; it < 8; it++) {                                            \
            const int u = tid + it * 256;                                           \
            const int part = u >> 10;                                               \
            const int v = u & 1023, o = v >> 3, s = v & 7;                          \
            const uint32_t dst = sb + MW2(_buf, part) + o * PITCH + s * 16;         \
            const uint16_t* srcb = part ? g_w2l : g_w2h;                            \
            CP16(dst, srcb + o * H1n + (kc) * 64 + s * 8);                          \
        }                                                                           \
        CPCOMMIT();                                                                 \
    } while (0)

    FILLW2(0);
    FILLW2(1);

    // GEMM1 epilogue: relu + bias -> s_h hi/lo (overlays W1 region)
    #pragma unroll
    for (int mi = 0; mi < 4; mi++) {
        const int o = ow * 64 + mi * 16 + (lane >> 2);
        const float bia0 = s_b1[o], bia1 = s_b1[o + 8];
        #pragma unroll
        for (int ni = 0; ni < 4; ni++) {
            const int n = nw * 32 + ni * 8 + (lane & 3) * 2;
            const float* a = acc1[mi * 4 + ni];
            const float v0 = fmaxf(a[0] + bia0, 0.f);
            const float v1 = fmaxf(a[1] + bia0, 0.f);
            const float v2 = fmaxf(a[2] + bia1, 0.f);
            const float v3 = fmaxf(a[3] + bia1, 0.f);
            *(uint32_t*)(smc + MH(0) + o * PITCH + n * 2)       = bfhi2(v0, v1);
            *(uint32_t*)(smc + MH(1) + o * PITCH + n * 2)       = bflo2(v0, v1);
            *(uint32_t*)(smc + MH(0) + (o + 8) * PITCH + n * 2) = bfhi2(v2, v3);
            *(uint32_t*)(smc + MH(1) + (o + 8) * PITCH + n * 2) = bflo2(v2, v3);
        }
    }

    // ---------- GEMM2 ----------
    const int ow2 = w >> 1;
    float acc2[8][4];
    #pragma unroll
    for (int i = 0; i < 8; i++)
        #pragma unroll
        for (int j = 0; j < 4; j++) acc2[i][j] = 0.f;

    for (int kc = 0; kc < 4; kc++) {
        const int buf = kc & 1;
        if (kc < 3) { CPWAIT(1); } else { CPWAIT(0); }
        __syncthreads();   // W2 arrival + h writes visible
        #pragma unroll
        for (int kk = 0; kk < 4; kk++) {
            uint32_t wh[2][4], wl[2][4];
            #pragma unroll
            for (int mi = 0; mi < 2; mi++) {
                const uint32_t row = ow2 * 32 + mi * 16 + (lane & 15);
                const uint32_t off = row * PITCH + kk * 32 + (lane >> 4) * 16;
                ldsm4(wh[mi], sb + MW2(buf, 0) + off);
                ldsm4(wl[mi], sb + MW2(buf, 1) + off);
            }
            uint32_t hh[4][2], hl[4][2];
            #pragma unroll
            for (int np = 0; np < 2; np++) {
                const uint32_t row  = kc * 64 + kk * 16 + ((lane >> 3) & 1) * 8 + (lane & 7);
                const uint32_t colb = (nw * 32 + np * 16) * 2 + (lane >> 4) * 16;
                uint32_t r[4];
                ldsm4t(r, sb + MH(0) + row * PITCH + colb);
                hh[np * 2][0] = r[0]; hh[np * 2][1] = r[1];
                hh[np * 2 + 1][0] = r[2]; hh[np * 2 + 1][1] = r[3];
                ldsm4t(r, sb + MH(1) + row * PITCH + colb);
                hl[np * 2][0] = r[0]; hl[np * 2][1] = r[1];
                hl[np * 2 + 1][0] = r[2]; hl[np * 2 + 1][1] = r[3];
            }
            #pragma unroll
            for (int mi = 0; mi < 2; mi++)
                #pragma unroll
                for (int ni = 0; ni < 4; ni++) {
                    mma_bf16(acc2[mi * 4 + ni], wh[mi], hh[ni]);
                    mma_bf16(acc2[mi * 4 + ni], wh[mi], hl[ni]);
                    mma_bf16(acc2[mi * 4 + ni], wl[mi], hh[ni]);
                }
        }
        if (kc < 2) {
            __syncthreads();
            FILLW2(kc + 2);
        }
    }
    #undef FILLW2

    // ---------- output ----------
    #pragma unroll
    for (int mi = 0; mi < 2; mi++) {
        const int o = ow2 * 32 + mi * 16 + (lane >> 2);
        const float bia0 = s_b2[o], bia1 = s_b2[o + 8];
        #pragma unroll
        for (int ni = 0; ni < 4; ni++) {
            const int n = n0 + nw * 32 + ni * 8 + (lane & 3) * 2;
            const float* a = acc2[mi * 4 + ni];
            float2 v0, v1;
            v0.x = fmaxf(a[0] + bia0, 0.f);
            v0.y = fmaxf(a[1] + bia0, 0.f);
            v1.x = fmaxf(a[2] + bia1, 0.f);
            v1.y = fmaxf(a[3] + bia1, 0.f);
            *(float2*)&out[((size_t)b * H2n + o) * Nn + n]     = v0;
            *(float2*)&out[((size_t)b * H2n + o + 8) * Nn + n] = v1;
        }
    }
}

extern "C" void kernel_launch(void* const* d_in, const int* in_sizes, int n_in,
                              void* d_out, int out_size)
{
    const float* xyz1 = (const float*)d_in[0];
    const float* xyz2 = (const float*)d_in[1];
    const float* p1   = (const float*)d_in[2];
    const float* p2   = (const float*)d_in[3];
    const float* W1   = (const float*)d_in[4];
    const float* b1   = (const float*)d_in[5];
    const float* W2   = (const float*)d_in[6];
    const float* b2   = (const float*)d_in[7];
    float* out = (float*)d_out;

    cudaFuncSetAttribute(interp_tc, cudaFuncAttributeMaxDynamicSharedMemorySize, ISMB);
    cudaFuncSetAttribute(mlp_tc,    cudaFuncAttributeMaxDynamicSharedMemorySize, MSMB);

    uint16_t* p2h; cudaGetSymbolAddress((void**)&p2h, g_p2h);
    uint16_t* p2l; cudaGetSymbolAddress((void**)&p2l, g_p2l);
    uint16_t* p1h; cudaGetSymbolAddress((void**)&p1h, g_p1h);
    uint16_t* p1l; cudaGetSymbolAddress((void**)&p1l, g_p1l);
    uint16_t* w1h; cudaGetSymbolAddress((void**)&w1h, g_w1h);
    uint16_t* w1l; cudaGetSymbolAddress((void**)&w1l, g_w1l);
    uint16_t* w2h; cudaGetSymbolAddress((void**)&w2h, g_w2h);
    uint16_t* w2l; cudaGetSymbolAddress((void**)&w2l, g_w2l);

    split_kernel<<<(Bn * C2n * Mn) / 1024, 256>>>(p2, p2h, p2l);
    split_kernel<<<(Bn * C1n * Nn) / 1024, 256>>>(p1, p1h, p1l);
    split_kernel<<<(H1n * CINn) / 1024, 256>>>(W1, w1h, w1l);
    split_kernel<<<(H2n * H1n) / 1024, 256>>>(W2, w2h, w2l);

    dim3 grid(Nn / 64, Bn);
    interp_tc<<<grid, 256, ISMB>>>(xyz1, xyz2);
    mlp_tc<<<grid, 256, MSMB>>>(b1, b2, out);
}

// round 5
// speedup vs baseline: 1.0600x; 1.0600x over previous
#include <cuda_runtime.h>
#include <cuda_bf16.h>
#include <cstdint>

// Problem constants
#define Bn   16
#define Nn   4096
#define Mn   1024
#define C1n  128
#define C2n  256
#define CINn 384
#define H1n  256
#define H2n  128

#define PITCH 144   // bytes per smem row (72 bf16): conflict-free ldmatrix

// ---------------- helpers ----------------
__device__ __forceinline__ uint32_t smem_u32(const void* p) {
    uint32_t a;
    asm("{ .reg .u64 t; cvta.to.shared.u64 t, %1; cvt.u32.u64 %0, t; }" : "=r"(a) : "l"(p));
    return a;
}
__device__ __forceinline__ void ldsm4(uint32_t* r, uint32_t addr) {
    asm volatile("ldmatrix.sync.aligned.m8n8.x4.shared.b16 {%0,%1,%2,%3}, [%4];"
        : "=r"(r[0]), "=r"(r[1]), "=r"(r[2]), "=r"(r[3]) : "r"(addr));
}
__device__ __forceinline__ void ldsm4t(uint32_t* r, uint32_t addr) {
    asm volatile("ldmatrix.sync.aligned.m8n8.x4.trans.shared.b16 {%0,%1,%2,%3}, [%4];"
        : "=r"(r[0]), "=r"(r[1]), "=r"(r[2]), "=r"(r[3]) : "r"(addr));
}
__device__ __forceinline__ void mma_bf16(float* d, const uint32_t* a, const uint32_t* b) {
    asm volatile("mma.sync.aligned.m16n8k16.row.col.f32.bf16.bf16.f32 "
        "{%0,%1,%2,%3}, {%4,%5,%6,%7}, {%8,%9}, {%0,%1,%2,%3};"
        : "+f"(d[0]), "+f"(d[1]), "+f"(d[2]), "+f"(d[3])
        : "r"(a[0]), "r"(a[1]), "r"(a[2]), "r"(a[3]), "r"(b[0]), "r"(b[1]));
}
// pack two floats: hi = truncated bf16 pair, lo = bf16 of exact remainder
__device__ __forceinline__ uint32_t bfhi2(float a, float b) {
    return __byte_perm(__float_as_uint(a), __float_as_uint(b), 0x7632);
}
__device__ __forceinline__ uint32_t bflo2(float a, float b) {
    const float la = a - __uint_as_float(__float_as_uint(a) & 0xFFFF0000u);
    const float lb = b - __uint_as_float(__float_as_uint(b) & 0xFFFF0000u);
    __nv_bfloat162 p = __floats2bfloat162_rn(la, lb);
    return *(uint32_t*)&p;
}

// scratch: interpolated features [B][C2][N] fp32
__device__ float g_interp[(size_t)Bn * C2n * Nn];

// ================= Kernel 1: interpolation via mma.sync =================
// CTA tile: 64 n-points x 256 channels, K = M = 1024 in 64-chunks, double-buffered.
// A = inv-dist weights [64 n][64 k] hi/lo   B = p2 [256 c][64 k] hi/lo
#define IA(buf, part)  ((buf) * 18432 + (part) * 9216)
#define IB(buf, part)  (36864 + (buf) * 73728 + (part) * 36864)
#define IOFF_X2  184320
#define IOFF_DS  196608
#define IOFF_DEN 197632
#define ISMB     197888

__global__ __launch_bounds__(256, 1)
void interp_tc(const float* __restrict__ xyz1,
               const float* __restrict__ xyz2,
               const float* __restrict__ p2)
{
    extern __shared__ char smc[];
    const uint32_t sb = smem_u32(smc);
    float* s_x2  = (float*)(smc + IOFF_X2);
    float* s_ds  = (float*)(smc + IOFF_DS);
    float* s_den = (float*)(smc + IOFF_DEN);

    const int tid = threadIdx.x, w = tid >> 5, lane = tid & 31;
    const int b = blockIdx.y, n0 = blockIdx.x * 64;

    for (int i = tid; i < Mn * 3; i += 256)
        s_x2[i] = xyz2[(size_t)b * Mn * 3 + i];
    __syncthreads();

    const int nf = tid & 63;        // point this thread generates weights for
    const int g  = tid >> 6;        // 16-m group within chunk
    const float px = xyz1[((size_t)b * Nn + n0 + nf) * 3 + 0];
    const float py = xyz1[((size_t)b * Nn + n0 + nf) * 3 + 1];
    const float pz = xyz1[((size_t)b * Nn + n0 + nf) * 3 + 2];
    float dsum = 0.f;

    const int mw = w & 1, cw = w >> 1;   // warp tile: 32 n x 64 c
    float acc[16][4];
    #pragma unroll
    for (int i = 0; i < 16; i++)
        #pragma unroll
        for (int j = 0; j < 4; j++) acc[i][j] = 0.f;

    // ---------- fill chunk ch into buffer ch&1 ----------
    #define FILL(ch) do {                                                          \
        const int _buf = (ch) & 1, _m0 = (ch) * 64;                                \
        _Pragma("unroll")                                                          \
        for (int j = 0; j < 2; j++) {                                              \
            const int mb = g * 16 + j * 8;                                         \
            float iv[8];                                                           \
            _Pragma("unroll")                                                      \
            for (int t = 0; t < 8; t++) {                                          \
                const int m = _m0 + mb + t;                                        \
                const float dx = px - s_x2[m * 3 + 0];                             \
                const float dy = py - s_x2[m * 3 + 1];                             \
                const float dz = pz - s_x2[m * 3 + 2];                             \
                const float d2 = fmaf(dx, dx, fmaf(dy, dy, fmaf(dz, dz, 1e-16f))); \
                iv[t] = rsqrtf(d2);                                                \
                dsum += iv[t];                                                     \
            }                                                                      \
            uint4 hv, lv;                                                          \
            hv.x = bfhi2(iv[0], iv[1]); hv.y = bfhi2(iv[2], iv[3]);                \
            hv.z = bfhi2(iv[4], iv[5]); hv.w = bfhi2(iv[6], iv[7]);                \
            lv.x = bflo2(iv[0], iv[1]); lv.y = bflo2(iv[2], iv[3]);                \
            lv.z = bflo2(iv[4], iv[5]); lv.w = bflo2(iv[6], iv[7]);                \
            *(uint4*)(smc + IA(_buf, 0) + nf * PITCH + mb * 2) = hv;               \
            *(uint4*)(smc + IA(_buf, 1) + nf * PITCH + mb * 2) = lv;               \
        }                                                                          \
        _Pragma("unroll")                                                          \
        for (int it = 0; it < 16; it++) {                                          \
            const int u = tid + it * 256;                                          \
            const int c = u >> 4, q = u & 15;                                      \
            const float4 v = *(const float4*)&p2[((size_t)b * C2n + c) * Mn + _m0 + q * 4]; \
            uint2 hv, lv;                                                          \
            hv.x = bfhi2(v.x, v.y); hv.y = bfhi2(v.z, v.w);                        \
            lv.x = bflo2(v.x, v.y); lv.y = bflo2(v.z, v.w);                        \
            *(uint2*)(smc + IB(_buf, 0) + c * PITCH + q * 8) = hv;                 \
            *(uint2*)(smc + IB(_buf, 1) + c * PITCH + q * 8) = lv;                 \
        }                                                                          \
    } while (0)

    FILL(0);
    __syncthreads();

    for (int ch = 0; ch < 16; ch++) {
        const int buf = ch & 1;
        // ---- MMA on buf (pass-major: consecutive HMMAs hit different accs) ----
        #pragma unroll
        for (int kk = 0; kk < 4; kk++) {
            uint32_t ah[2][4], al[2][4];
            #pragma unroll
            for (int mt = 0; mt < 2; mt++) {
                const uint32_t row = mw * 32 + mt * 16 + (lane & 15);
                const uint32_t off = row * PITCH + kk * 32 + (lane >> 4) * 16;
                ldsm4(ah[mt], sb + IA(buf, 0) + off);
                ldsm4(al[mt], sb + IA(buf, 1) + off);
            }
            uint32_t bh[8][2], bl[8][2];
            #pragma unroll
            for (int cp = 0; cp < 4; cp++) {
                const uint32_t row = cw * 64 + cp * 16 + (lane >> 4) * 8 + (lane & 7);
                const uint32_t off = row * PITCH + kk * 32 + ((lane >> 3) & 1) * 16;
                uint32_t r[4];
                ldsm4(r, sb + IB(buf, 0) + off);
                bh[cp * 2][0] = r[0]; bh[cp * 2][1] = r[1];
                bh[cp * 2 + 1][0] = r[2]; bh[cp * 2 + 1][1] = r[3];
                ldsm4(r, sb + IB(buf, 1) + off);
                bl[cp * 2][0] = r[0]; bl[cp * 2][1] = r[1];
                bl[cp * 2 + 1][0] = r[2]; bl[cp * 2 + 1][1] = r[3];
            }
            // pass 1: hi x hi  (16 independent accumulators)
            #pragma unroll
            for (int mt = 0; mt < 2; mt++)
                #pragma unroll
                for (int ct = 0; ct < 8; ct++)
                    mma_bf16(acc[mt * 8 + ct], ah[mt], bh[ct]);
            // pass 2: hi x lo
            #pragma unroll
            for (int mt = 0; mt < 2; mt++)
                #pragma unroll
                for (int ct = 0; ct < 8; ct++)
                    mma_bf16(acc[mt * 8 + ct], ah[mt], bl[ct]);
            // pass 3: lo x hi
            #pragma unroll
            for (int mt = 0; mt < 2; mt++)
                #pragma unroll
                for (int ct = 0; ct < 8; ct++)
                    mma_bf16(acc[mt * 8 + ct], al[mt], bh[ct]);
        }
        // ---- fill next chunk (other buffer) ----
        if (ch < 15) FILL(ch + 1);
        __syncthreads();
    }
    #undef FILL

    // denominator
    s_ds[tid] = dsum;
    __syncthreads();
    if (tid < 64)
        s_den[tid] = 1.0f / (s_ds[tid] + s_ds[tid + 64] + s_ds[tid + 128] + s_ds[tid + 192]);
    __syncthreads();

    // epilogue: scale and store
    #pragma unroll
    for (int mt = 0; mt < 2; mt++) {
        const int nl = mw * 32 + mt * 16 + (lane >> 2);
        const float i0 = s_den[nl], i1 = s_den[nl + 8];
        #pragma unroll
        for (int ct = 0; ct < 8; ct++) {
            const int c = cw * 64 + ct * 8 + (lane & 3) * 2;
            float* d0 = &g_interp[((size_t)b * C2n + c) * Nn + n0];
            float* d1 = &g_interp[((size_t)b * C2n + c + 1) * Nn + n0];
            const float* a = acc[mt * 8 + ct];
            d0[nl]     = a[0] * i0;
            d1[nl]     = a[1] * i0;
            d0[nl + 8] = a[2] * i1;
            d1[nl + 8] = a[3] * i1;
        }
    }
}

// ================= Kernel 2: fused 2-layer MLP via mma.sync =================
// CTA: 64 n-points. GEMM1: [256 o] x [64 n] x K=384; GEMM2: [128 o] x [64 n] x K=256.
#define MW(buf, part)  ((buf) * 73728 + (part) * 36864)        // W1 chunk [256][72]
#define MX(buf, part)  (147456 + (buf) * 18432 + (part) * 9216) // x chunk [64][72]
#define MH(part)       ((part) * 36864)                         // h [256][72] (overlays MW)
#define MW2(part)      (147456 + (part) * 18432)                // W2 chunk [128][72] (overlays MX)
#define MOFF_B1  184320
#define MOFF_B2  185344
#define MSMB     185856

__global__ __launch_bounds__(256, 1)
void mlp_tc(const float* __restrict__ p1,
            const float* __restrict__ W1,
            const float* __restrict__ b1,
            const float* __restrict__ W2,
            const float* __restrict__ b2,
            float* __restrict__ out)
{
    extern __shared__ char smc[];
    const uint32_t sb = smem_u32(smc);
    float* s_b1 = (float*)(smc + MOFF_B1);
    float* s_b2 = (float*)(smc + MOFF_B2);

    const int tid = threadIdx.x, w = tid >> 5, lane = tid & 31;
    const int b = blockIdx.y, n0 = blockIdx.x * 64;

    s_b1[tid] = b1[tid];
    if (tid < H2n) s_b2[tid] = b2[tid];

    const int ow = w >> 1, nw = w & 1;   // GEMM1 warp: 64 o x 32 n

    // ---------- GEMM1 fill: W1 chunk + x chunk ----------
    #define FILL1(kc) do {                                                          \
        const int _buf = (kc) & 1;                                                  \
        _Pragma("unroll")                                                           \
        for (int it = 0; it < 16; it++) {                                           \
            const int u = tid + it * 256;                                           \
            const int o = u >> 4, q = u & 15;                                       \
            const float4 v = *(const float4*)&W1[(size_t)o * CINn + (kc) * 64 + q * 4]; \
            uint2 hv, lv;                                                           \
            hv.x = bfhi2(v.x, v.y); hv.y = bfhi2(v.z, v.w);                         \
            lv.x = bflo2(v.x, v.y); lv.y = bflo2(v.z, v.w);                         \
            *(uint2*)(smc + MW(_buf, 0) + o * PITCH + q * 8) = hv;                  \
            *(uint2*)(smc + MW(_buf, 1) + o * PITCH + q * 8) = lv;                  \
        }                                                                           \
        _Pragma("unroll")                                                           \
        for (int it = 0; it < 4; it++) {                                            \
            const int u = tid + it * 256;                                           \
            const int k = u >> 4, q = u & 15;                                       \
            const int c = (kc) * 64 + k;                                            \
            const float* src = (c < C1n)                                            \
                ? &p1[((size_t)b * C1n + c) * Nn]                                   \
                : &g_interp[((size_t)b * C2n + (c - C1n)) * Nn];                    \
            const float4 v = *(const float4*)&src[n0 + q * 4];                      \
            uint2 hv, lv;                                                           \
            hv.x = bfhi2(v.x, v.y); hv.y = bfhi2(v.z, v.w);                         \
            lv.x = bflo2(v.x, v.y); lv.y = bflo2(v.z, v.w);                         \
            *(uint2*)(smc + MX(_buf, 0) + k * PITCH + q * 8) = hv;                  \
            *(uint2*)(smc + MX(_buf, 1) + k * PITCH + q * 8) = lv;                  \
        }                                                                           \
    } while (0)

    float acc1[16][4];
    #pragma unroll
    for (int i = 0; i < 16; i++)
        #pragma unroll
        for (int j = 0; j < 4; j++) acc1[i][j] = 0.f;

    FILL1(0);
    __syncthreads();

    for (int kc = 0; kc < 6; kc++) {
        const int buf = kc & 1;
        #pragma unroll
        for (int kk = 0; kk < 4; kk++) {
            uint32_t wh[4][4], wl[4][4];
            #pragma unroll
            for (int mi = 0; mi < 4; mi++) {
                const uint32_t row = ow * 64 + mi * 16 + (lane & 15);
                const uint32_t off = row * PITCH + kk * 32 + (lane >> 4) * 16;
                ldsm4(wh[mi], sb + MW(buf, 0) + off);
                ldsm4(wl[mi], sb + MW(buf, 1) + off);
            }
            uint32_t xh[4][2], xl[4][2];
            #pragma unroll
            for (int np = 0; np < 2; np++) {
                const uint32_t row  = kk * 16 + ((lane >> 3) & 1) * 8 + (lane & 7);
                const uint32_t colb = (nw * 32 + np * 16) * 2 + (lane >> 4) * 16;
                uint32_t r[4];
                ldsm4t(r, sb + MX(buf, 0) + row * PITCH + colb);
                xh[np * 2][0] = r[0]; xh[np * 2][1] = r[1];
                xh[np * 2 + 1][0] = r[2]; xh[np * 2 + 1][1] = r[3];
                ldsm4t(r, sb + MX(buf, 1) + row * PITCH + colb);
                xl[np * 2][0] = r[0]; xl[np * 2][1] = r[1];
                xl[np * 2 + 1][0] = r[2]; xl[np * 2 + 1][1] = r[3];
            }
            // pass-major: independent consecutive HMMAs
            #pragma unroll
            for (int mi = 0; mi < 4; mi++)
                #pragma unroll
                for (int ni = 0; ni < 4; ni++)
                    mma_bf16(acc1[mi * 4 + ni], wh[mi], xh[ni]);
            #pragma unroll
            for (int mi = 0; mi < 4; mi++)
                #pragma unroll
                for (int ni = 0; ni < 4; ni++)
                    mma_bf16(acc1[mi * 4 + ni], wh[mi], xl[ni]);
            #pragma unroll
            for (int mi = 0; mi < 4; mi++)
                #pragma unroll
                for (int ni = 0; ni < 4; ni++)
                    mma_bf16(acc1[mi * 4 + ni], wl[mi], xh[ni]);
        }
        if (kc < 5) FILL1(kc + 1);
        __syncthreads();
    }
    #undef FILL1

    // ---------- GEMM1 epilogue: relu + bias -> s_h (hi/lo), overlays MW ----------
    #pragma unroll
    for (int mi = 0; mi < 4; mi++) {
        const int o = ow * 64 + mi * 16 + (lane >> 2);
        const float bia0 = s_b1[o], bia1 = s_b1[o + 8];
        #pragma unroll
        for (int ni = 0; ni < 4; ni++) {
            const int n = nw * 32 + ni * 8 + (lane & 3) * 2;
            const float* a = acc1[mi * 4 + ni];
            const float v0 = fmaxf(a[0] + bia0, 0.f);
            const float v1 = fmaxf(a[1] + bia0, 0.f);
            const float v2 = fmaxf(a[2] + bia1, 0.f);
            const float v3 = fmaxf(a[3] + bia1, 0.f);
            *(uint32_t*)(smc + MH(0) + o * PITCH + n * 2)       = bfhi2(v0, v1);
            *(uint32_t*)(smc + MH(1) + o * PITCH + n * 2)       = bflo2(v0, v1);
            *(uint32_t*)(smc + MH(0) + (o + 8) * PITCH + n * 2) = bfhi2(v2, v3);
            *(uint32_t*)(smc + MH(1) + (o + 8) * PITCH + n * 2) = bflo2(v2, v3);
        }
    }

    // ---------- GEMM2 ----------
    const int ow2 = w >> 1;   // 32 o per warp
    float acc2[8][4];
    #pragma unroll
    for (int i = 0; i < 8; i++)
        #pragma unroll
        for (int j = 0; j < 4; j++) acc2[i][j] = 0.f;

    for (int kc = 0; kc < 4; kc++) {
        __syncthreads();   // previous compute done reading s_w2 / first: s_h written
        #pragma unroll
        for (int it = 0; it < 8; it++) {
            const int u = tid + it * 256;
            const int o = u >> 4, q = u & 15;
            const float4 v = *(const float4*)&W2[(size_t)o * H1n + kc * 64 + q * 4];
            uint2 hv, lv;
            hv.x = bfhi2(v.x, v.y); hv.y = bfhi2(v.z, v.w);
            lv.x = bflo2(v.x, v.y); lv.y = bflo2(v.z, v.w);
            *(uint2*)(smc + MW2(0) + o * PITCH + q * 8) = hv;
            *(uint2*)(smc + MW2(1) + o * PITCH + q * 8) = lv;
        }
        __syncthreads();
        #pragma unroll
        for (int kk = 0; kk < 4; kk++) {
            uint32_t wh[2][4], wl[2][4];
            #pragma unroll
            for (int mi = 0; mi < 2; mi++) {
                const uint32_t row = ow2 * 32 + mi * 16 + (lane & 15);
                const uint32_t off = row * PITCH + kk * 32 + (lane >> 4) * 16;
                ldsm4(wh[mi], sb + MW2(0) + off);
                ldsm4(wl[mi], sb + MW2(1) + off);
            }
            uint32_t hh[4][2], hl[4][2];
            #pragma unroll
            for (int np = 0; np < 2; np++) {
                const uint32_t row  = kc * 64 + kk * 16 + ((lane >> 3) & 1) * 8 + (lane & 7);
                const uint32_t colb = (nw * 32 + np * 16) * 2 + (lane >> 4) * 16;
                uint32_t r[4];
                ldsm4t(r, sb + MH(0) + row * PITCH + colb);
                hh[np * 2][0] = r[0]; hh[np * 2][1] = r[1];
                hh[np * 2 + 1][0] = r[2]; hh[np * 2 + 1][1] = r[3];
                ldsm4t(r, sb + MH(1) + row * PITCH + colb);
                hl[np * 2][0] = r[0]; hl[np * 2][1] = r[1];
                hl[np * 2 + 1][0] = r[2]; hl[np * 2 + 1][1] = r[3];
            }
            // pass-major
            #pragma unroll
            for (int mi = 0; mi < 2; mi++)
                #pragma unroll
                for (int ni = 0; ni < 4; ni++)
                    mma_bf16(acc2[mi * 4 + ni], wh[mi], hh[ni]);
            #pragma unroll
            for (int mi = 0; mi < 2; mi++)
                #pragma unroll
                for (int ni = 0; ni < 4; ni++)
                    mma_bf16(acc2[mi * 4 + ni], wh[mi], hl[ni]);
            #pragma unroll
            for (int mi = 0; mi < 2; mi++)
                #pragma unroll
                for (int ni = 0; ni < 4; ni++)
                    mma_bf16(acc2[mi * 4 + ni], wl[mi], hh[ni]);
        }
    }

    // ---------- output ----------
    #pragma unroll
    for (int mi = 0; mi < 2; mi++) {
        const int o = ow2 * 32 + mi * 16 + (lane >> 2);
        const float bia0 = s_b2[o], bia1 = s_b2[o + 8];
        #pragma unroll
        for (int ni = 0; ni < 4; ni++) {
            const int n = n0 + nw * 32 + ni * 8 + (lane & 3) * 2;
            const float* a = acc2[mi * 4 + ni];
            float2 v0, v1;
            v0.x = fmaxf(a[0] + bia0, 0.f);
            v0.y = fmaxf(a[1] + bia0, 0.f);
            v1.x = fmaxf(a[2] + bia1, 0.f);
            v1.y = fmaxf(a[3] + bia1, 0.f);
            *(float2*)&out[((size_t)b * H2n + o) * Nn + n]     = v0;
            *(float2*)&out[((size_t)b * H2n + o + 8) * Nn + n] = v1;
        }
    }
}

extern "C" void kernel_launch(void* const* d_in, const int* in_sizes, int n_in,
                              void* d_out, int out_size)
{
    const float* xyz1 = (const float*)d_in[0];
    const float* xyz2 = (const float*)d_in[1];
    const float* p1   = (const float*)d_in[2];
    const float* p2   = (const float*)d_in[3];
    const float* W1   = (const float*)d_in[4];
    const float* b1   = (const float*)d_in[5];
    const float* W2   = (const float*)d_in[6];
    const float* b2   = (const float*)d_in[7];
    float* out = (float*)d_out;

    cudaFuncSetAttribute(interp_tc, cudaFuncAttributeMaxDynamicSharedMemorySize, ISMB);
    cudaFuncSetAttribute(mlp_tc,    cudaFuncAttributeMaxDynamicSharedMemorySize, MSMB);

    dim3 grid(Nn / 64, Bn);
    interp_tc<<<grid, 256, ISMB>>>(xyz1, xyz2, p2);
    mlp_tc<<<grid, 256, MSMB>>>(p1, W1, b1, W2, b2, out);
}